// round 15
// baseline (speedup 1.0000x reference)
#include <cuda_runtime.h>
#include <math.h>

// Shapes: B=2, T=16, C=30, H=W=64.  NIMG = B*T = 32 images, NPIX = 4096.
// Deform conv input is the reshape-scrambled view xr[j][c'] with
//   f1 = j*30+c', b = f1/480, c = (f1%480)/16, t = f1%16  ->  x[b][t][c].
// Tiles are gathered directly from x.  conv1 (offset/mask) is fused into the
// deform kernel: one tile load serves both, om lives in thread-local memory.

#define NIMG 32
#define NPIX 4096
#define XSTR 36   // smem per-pixel stride (floats): 9 float4s -> all 8 bank groups hit.

typedef unsigned long long ull;

// packed-pair FMA: d.lo += a.lo*b.lo, d.hi += a.hi*b.hi  (sm_100a f32x2)
#define FMA2(d, a, b) asm("fma.rn.f32x2 %0, %1, %2, %0;" : "+l"(d) : "l"(a), "l"(b))
#define ADD2(d, a)    asm("add.rn.f32x2 %0, %0, %1;" : "+l"(d) : "l"(a))

__device__ __forceinline__ ull bc2(float x) {
    ull r;
    asm("mov.b64 %0, {%1, %1};" : "=l"(r) : "r"(__float_as_uint(x)));
    return r;
}
__device__ __forceinline__ float lo2(ull v) { return __uint_as_float((unsigned)v); }
__device__ __forceinline__ float hi2(ull v) { return __uint_as_float((unsigned)(v >> 32)); }

// plane offset of scrambled channel cp for image j:  x[b][t][c] plane base
__device__ __forceinline__ int plane_off(int j, int cp) {
    int f1 = j * 30 + cp;
    int b = (f1 >= 480) ? 1 : 0;
    int rem = f1 - b * 480;
    int c = rem >> 4;
    int tt = rem & 15;
    return ((b * 16 + tt) * 30 + c) * NPIX;
}

// ---------------- scratch (device globals; no runtime allocation) -------------
__device__ float g_y1[NIMG * 30 * NPIX];                   // deform+comp output
// packed weights: rows indexed by absolute channel c, outputs consecutive (pairs)
__device__ __align__(16) float g_Wc2[9 * 32 * 32];         // [tap][c][o] o-padded to 32
__device__ __align__(16) float g_Wk2[9 * 32 * 28];         // [tap][c][o] o-padded to 28
__device__ float g_sums[32];                               // BN sum / sumsq per channel

// ---------------- K0: weight prep + zero stats --------------------------------
__global__ void k_prep(const float* __restrict__ comp_w, const float* __restrict__ conv_w,
                       const float* __restrict__ p_w, const float* __restrict__ m_w) {
    int t = blockIdx.x * blockDim.x + threadIdx.x;
    const int NW2C = 9 * 32 * 32;          // 9216
    const int NW2K = 9 * 32 * 28;          // 8064
    if (t < NW2C) {
        int n = t >> 10;
        int r = t & 1023;
        int c = r >> 5;
        int o = r & 31;
        float acc = 0.f;
        if (c < 30 && o < 30) {
            for (int m = 0; m < 90; m++)
                acc += comp_w[o * 90 + m] * conv_w[(m * 30 + c) * 9 + n];
        }
        g_Wc2[t] = acc;
    } else if (t < NW2C + NW2K) {
        int u = t - NW2C;
        int n = u / 896;
        int r = u - n * 896;
        int c = r / 28;
        int o = r - c * 28;
        float v = 0.f;
        if (c < 30) {
            if (o < 18)      v = p_w[(o * 30 + c) * 9 + n];
            else if (o < 27) v = m_w[((o - 18) * 30 + c) * 9 + n];
        }
        g_Wk2[u] = v;
    } else if (t < NW2C + NW2K + 32) {
        g_sums[t - (NW2C + NW2K)] = 0.f;
    }
}

// ---------------- K1: FUSED offset/mask conv + deform sample + matvec -----------
#define DTS 36
// cold path: gather corner channels straight from scrambled x.
// Channels >=30 load via po[]=0 (finite garbage) and are killed by zero weights.
__device__ __forceinline__ void add_corner_x(float4* s, const float* __restrict__ x,
                                             const int* po, int qx, int qy,
                                             float g, int co) {
    if (qx >= 1 && qx <= 64 && qy >= 1 && qy <= 64) {
        int hw = (qx - 1) * 64 + (qy - 1);
#pragma unroll
        for (int q = 0; q < 4; q++) {
            int c0 = co + (q << 2);
            float4 v;
            v.x = x[po[c0]     + hw];
            v.y = x[po[c0 + 1] + hw];
            v.z = x[po[c0 + 2] + hw];
            v.w = x[po[c0 + 3] + hw];
            s[q].x += g * v.x; s[q].y += g * v.y;
            s[q].z += g * v.z; s[q].w += g * v.w;
        }
    }
}

__global__ void __launch_bounds__(512, 1) k_main(const float* __restrict__ x,
                                                 const float* __restrict__ p_b,
                                                 const float* __restrict__ m_b) {
    extern __shared__ float sm[];
    float* xt = sm;                        // [DTS*DTS*XSTR] = 186624 B
    float* wt = sm + DTS * DTS * XSTR;     // max(9*32*28, 9*32*32) = 36864 B
    int* po = (int*)(wt + 9 * 32 * 32);    // [32]
    int blk = blockIdx.x;
    int j = blk >> 2;
    int tile = blk & 3;
    int th0 = (tile >> 1) << 5;
    int tw0 = (tile & 1) << 5;
    int tx0 = th0 - 1;   // padded coord of smem row 0
    int ty0 = tw0 - 1;
    int tid = threadIdx.x;

    if (tid < 32) po[tid] = (tid < 30) ? plane_off(j, tid) : 0;
    __syncthreads();

    // ---- shared tile load (serves both conv phases) ----
    for (int pos = tid; pos < DTS * DTS; pos += 512) {
        int rr = pos / DTS, cc = pos % DTS;
        int qx = tx0 + rr, qy = ty0 + cc;
        float v[32];
        if (qx >= 1 && qx <= 64 && qy >= 1 && qy <= 64) {
            int hw = (qx - 1) * 64 + (qy - 1);
#pragma unroll
            for (int cp = 0; cp < 30; cp++) v[cp] = x[po[cp] + hw];
        } else {
#pragma unroll
            for (int cp = 0; cp < 30; cp++) v[cp] = 0.f;
        }
        v[30] = 0.f; v[31] = 0.f;
        float4* d = (float4*)(xt + pos * XSTR);
#pragma unroll
        for (int q = 0; q < 8; q++)
            d[q] = make_float4(v[4 * q], v[4 * q + 1], v[4 * q + 2], v[4 * q + 3]);
    }
    // conv1 weights first
    for (int p = tid; p < 9 * 32 * 28 / 4; p += 512)
        ((float4*)wt)[p] = ((const float4*)g_Wk2)[p];
    __syncthreads();

    int tx = tid & 31, ty = tid >> 5;      // ty 0..15
    int h0 = th0 + ty, h1 = h0 + 16;
    int w = tw0 + tx;

    // ================= phase 1: offset/mask conv (27 outs, 2 px) =================
    float om0[27], om1[27];   // runtime-indexed later -> local memory (by design)
    {
        ull A0[14], A1[14];
#pragma unroll
        for (int op = 0; op < 14; op++) { A0[op] = 0ull; A1[op] = 0ull; }

        for (int n = 0; n < 9; n++) {
            int i = n / 3;
            int jj = n - i * 3;
            // unpadded (h-1+i, w-1+jj) -> xt row ty+i+1, col tx+jj+1
            const float* b0 = xt + ((ty + i + 1) * DTS + (tx + jj + 1)) * XSTR;
            const float* b1 = b0 + 16 * DTS * XSTR;
            const float* wn = wt + n * 32 * 28;
#pragma unroll
            for (int half = 0; half < 2; half++) {
                int co = half << 4;
                float4 sA[4], sB[4];
                const float4* p0 = (const float4*)(b0 + co);
                const float4* p1 = (const float4*)(b1 + co);
#pragma unroll
                for (int q = 0; q < 4; q++) { sA[q] = p0[q]; sB[q] = p1[q]; }
#pragma unroll
                for (int i4 = 0; i4 < 4; i4++) {
                    float4 va = sA[i4], vb = sB[i4];
#pragma unroll
                    for (int comp = 0; comp < 4; comp++) {
                        float fa = comp == 0 ? va.x : comp == 1 ? va.y : comp == 2 ? va.z : va.w;
                        float fb = comp == 0 ? vb.x : comp == 1 ? vb.y : comp == 2 ? vb.z : vb.w;
                        int c = co + (i4 << 2) + comp;
                        ull ba = bc2(fa), bb = bc2(fb);
                        const ulonglong2* wc2 = (const ulonglong2*)(wn + c * 28);
#pragma unroll
                        for (int k = 0; k < 7; k++) {
                            ulonglong2 wv = wc2[k];
                            FMA2(A0[2 * k],     wv.x, ba);
                            FMA2(A0[2 * k + 1], wv.y, ba);
                            FMA2(A1[2 * k],     wv.x, bb);
                            FMA2(A1[2 * k + 1], wv.y, bb);
                        }
                    }
                }
            }
        }
#pragma unroll
        for (int o = 0; o < 18; o++) {
            float bo = p_b[o];
            om0[o] = ((o & 1) ? hi2(A0[o >> 1]) : lo2(A0[o >> 1])) + bo;
            om1[o] = ((o & 1) ? hi2(A1[o >> 1]) : lo2(A1[o >> 1])) + bo;
        }
#pragma unroll
        for (int o = 18; o < 27; o++) {
            float bo = m_b[o - 18];
            float z0 = ((o & 1) ? hi2(A0[o >> 1]) : lo2(A0[o >> 1])) + bo;
            float z1 = ((o & 1) ? hi2(A1[o >> 1]) : lo2(A1[o >> 1])) + bo;
            om0[o] = 1.f / (1.f + expf(-z0));
            om1[o] = 1.f / (1.f + expf(-z1));
        }
    }

    // swap in deform weights (Wk2 region is dead)
    __syncthreads();
    for (int p = tid; p < 9 * 32 * 32 / 4; p += 512)
        ((float4*)wt)[p] = ((const float4*)g_Wc2)[p];
    __syncthreads();

    // ================= phase 2: deform sample + matvec ===========================
    ull A0[15], A1[15];
#pragma unroll
    for (int op = 0; op < 15; op++) { A0[op] = 0ull; A1[op] = 0ull; }

    for (int n = 0; n < 9; n++) {
        int dxi = n / 3;
        int dyi = n - dxi * 3;
        const float* wn = wt + n * 32 * 32;

        // ---- pixel 0 geometry ----
        float ox0 = om0[n];
        float oy0 = om0[9 + n];
        float mk0 = om0[18 + n];
        float px0 = (float)(h0 + dxi) + ox0;
        float py0 = (float)(w + dyi) + oy0;
        float qfx0 = floorf(px0), qfy0 = floorf(py0);
        float lx0 = fminf(fmaxf(qfx0, 0.f), 65.f);
        float ly0 = fminf(fmaxf(qfy0, 0.f), 65.f);
        float rx0 = fminf(fmaxf(qfx0 + 1.f, 0.f), 65.f);
        float ry0 = fminf(fmaxf(qfy0 + 1.f, 0.f), 65.f);
        float pxc0 = fminf(fmaxf(px0, 0.f), 65.f);
        float pyc0 = fminf(fmaxf(py0, 0.f), 65.f);
        float gxl0 = 1.f + lx0 - pxc0, gxr0 = 1.f - rx0 + pxc0;
        float gyl0 = 1.f + ly0 - pyc0, gyr0 = 1.f - ry0 + pyc0;
        float g0lt = gxl0 * gyl0 * mk0, g0rb = gxr0 * gyr0 * mk0;
        float g0lb = gxl0 * gyr0 * mk0, g0rt = gxr0 * gyl0 * mk0;
        int a0x = (int)lx0, a0y = (int)ly0, b0x = (int)rx0, b0y = (int)ry0;
        bool f0 = (a0x >= tx0) & (b0x < tx0 + DTS) & (a0y >= ty0) & (b0y < ty0 + DTS);

        // ---- pixel 1 geometry ----
        float ox1 = om1[n];
        float oy1 = om1[9 + n];
        float mk1 = om1[18 + n];
        float px1 = (float)(h1 + dxi) + ox1;
        float py1 = (float)(w + dyi) + oy1;
        float qfx1 = floorf(px1), qfy1 = floorf(py1);
        float lx1 = fminf(fmaxf(qfx1, 0.f), 65.f);
        float ly1 = fminf(fmaxf(qfy1, 0.f), 65.f);
        float rx1 = fminf(fmaxf(qfx1 + 1.f, 0.f), 65.f);
        float ry1 = fminf(fmaxf(qfy1 + 1.f, 0.f), 65.f);
        float pxc1 = fminf(fmaxf(px1, 0.f), 65.f);
        float pyc1 = fminf(fmaxf(py1, 0.f), 65.f);
        float gxl1 = 1.f + lx1 - pxc1, gxr1 = 1.f - rx1 + pxc1;
        float gyl1 = 1.f + ly1 - pyc1, gyr1 = 1.f - ry1 + pyc1;
        float g1lt = gxl1 * gyl1 * mk1, g1rb = gxr1 * gyr1 * mk1;
        float g1lb = gxl1 * gyr1 * mk1, g1rt = gxr1 * gyl1 * mk1;
        int a1x = (int)lx1, a1y = (int)ly1, b1x = (int)rx1, b1y = (int)ry1;
        bool f1 = (a1x >= tx0) & (b1x < tx0 + DTS) & (a1y >= ty0) & (b1y < ty0 + DTS);

#pragma unroll
        for (int half = 0; half < 2; half++) {
            int co = half << 4;
            float4 sA[4], sB[4];

            if (f0) {
                const float4* A = (const float4*)(xt + ((a0x - tx0) * DTS + (a0y - ty0)) * XSTR + co);
                const float4* B = (const float4*)(xt + ((b0x - tx0) * DTS + (b0y - ty0)) * XSTR + co);
                const float4* C = (const float4*)(xt + ((a0x - tx0) * DTS + (b0y - ty0)) * XSTR + co);
                const float4* D = (const float4*)(xt + ((b0x - tx0) * DTS + (a0y - ty0)) * XSTR + co);
#pragma unroll
                for (int q = 0; q < 4; q++) {
                    float4 a = A[q], b = B[q], c = C[q], d = D[q];
                    sA[q].x = g0lt * a.x + g0rb * b.x + g0lb * c.x + g0rt * d.x;
                    sA[q].y = g0lt * a.y + g0rb * b.y + g0lb * c.y + g0rt * d.y;
                    sA[q].z = g0lt * a.z + g0rb * b.z + g0lb * c.z + g0rt * d.z;
                    sA[q].w = g0lt * a.w + g0rb * b.w + g0lb * c.w + g0rt * d.w;
                }
            } else {
#pragma unroll
                for (int q = 0; q < 4; q++) sA[q] = make_float4(0.f, 0.f, 0.f, 0.f);
                add_corner_x(sA, x, po, a0x, a0y, g0lt, co);
                add_corner_x(sA, x, po, b0x, b0y, g0rb, co);
                add_corner_x(sA, x, po, a0x, b0y, g0lb, co);
                add_corner_x(sA, x, po, b0x, a0y, g0rt, co);
            }

            if (f1) {
                const float4* A = (const float4*)(xt + ((a1x - tx0) * DTS + (a1y - ty0)) * XSTR + co);
                const float4* B = (const float4*)(xt + ((b1x - tx0) * DTS + (b1y - ty0)) * XSTR + co);
                const float4* C = (const float4*)(xt + ((a1x - tx0) * DTS + (b1y - ty0)) * XSTR + co);
                const float4* D = (const float4*)(xt + ((b1x - tx0) * DTS + (a1y - ty0)) * XSTR + co);
#pragma unroll
                for (int q = 0; q < 4; q++) {
                    float4 a = A[q], b = B[q], c = C[q], d = D[q];
                    sB[q].x = g1lt * a.x + g1rb * b.x + g1lb * c.x + g1rt * d.x;
                    sB[q].y = g1lt * a.y + g1rb * b.y + g1lb * c.y + g1rt * d.y;
                    sB[q].z = g1lt * a.z + g1rb * b.z + g1lb * c.z + g1rt * d.z;
                    sB[q].w = g1lt * a.w + g1rb * b.w + g1lb * c.w + g1rt * d.w;
                }
            } else {
#pragma unroll
                for (int q = 0; q < 4; q++) sB[q] = make_float4(0.f, 0.f, 0.f, 0.f);
                add_corner_x(sB, x, po, a1x, a1y, g1lt, co);
                add_corner_x(sB, x, po, b1x, b1y, g1rb, co);
                add_corner_x(sB, x, po, a1x, b1y, g1lb, co);
                add_corner_x(sB, x, po, b1x, a1y, g1rt, co);
            }

#pragma unroll
            for (int i4 = 0; i4 < 4; i4++) {
                float4 va = sA[i4], vb = sB[i4];
#pragma unroll
                for (int comp = 0; comp < 4; comp++) {
                    float fa = comp == 0 ? va.x : comp == 1 ? va.y : comp == 2 ? va.z : va.w;
                    float fb = comp == 0 ? vb.x : comp == 1 ? vb.y : comp == 2 ? vb.z : vb.w;
                    int c = co + (i4 << 2) + comp;
                    ull ba = bc2(fa), bb = bc2(fb);
                    const float* wrow = wn + c * 32;
                    const ulonglong2* wc2 = (const ulonglong2*)wrow;
#pragma unroll
                    for (int k = 0; k < 7; k++) {
                        ulonglong2 wv = wc2[k];
                        FMA2(A0[2 * k],     wv.x, ba);
                        FMA2(A0[2 * k + 1], wv.y, ba);
                        FMA2(A1[2 * k],     wv.x, bb);
                        FMA2(A1[2 * k + 1], wv.y, bb);
                    }
                    ull w14 = *(const ull*)(wrow + 28);   // pair (o=28,29)
                    FMA2(A0[14], w14, ba);
                    FMA2(A1[14], w14, bb);
                }
            }
        }
    }

    int hw0 = h0 * 64 + w;
    float* yb0 = g_y1 + (size_t)j * 30 * NPIX + hw0;
    float* yb1 = yb0 + 16 * 64;
#pragma unroll
    for (int op = 0; op < 15; op++) {
        yb0[(size_t)(2 * op)     * NPIX] = lo2(A0[op]);
        yb0[(size_t)(2 * op + 1) * NPIX] = hi2(A0[op]);
        yb1[(size_t)(2 * op)     * NPIX] = lo2(A1[op]);
        yb1[(size_t)(2 * op + 1) * NPIX] = hi2(A1[op]);
    }
}

// ---------------- K3: spec conv, 3 d-outputs/thread, immediate-consume window ---
// Per ti: load 5 d-values + 3 weight rows once, feed 3 outputs, discard.
// Loads/output -> ~27; weight LDS/output -> 4; regs ~95 (R13 measured 78 + A2).
__global__ void __launch_bounds__(256) k_spec(const float* __restrict__ spec_w,
                                              float* __restrict__ out) {
    __shared__ float sw2[48 * 16];   // transposed: [c=ti*3+kd][to]
    __shared__ float bsum[32];
    int tid = threadIdx.x;
    for (int p = tid; p < 768; p += 256) {
        int to = p / 48, c = p - to * 48;
        sw2[c * 16 + to] = spec_w[p];
    }
    if (tid < 32) bsum[tid] = 0.f;
    __syncthreads();

    int bx = blockIdx.x;             // 320 = 2 b * 10 dchunk * 16 hw-blocks
    int b  = bx / 160;
    int r  = bx - b * 160;
    int dc = r >> 4;                 // 0..9
    int hw = ((r & 15) << 8) + tid;
    int d0 = dc * 3;                 // 0,3,...,27

    const float* yb = g_y1 + (size_t)b * 16 * 30 * NPIX + hw;

    ull A0[8], A1[8], A2[8], S[8], Q[8];
#pragma unroll
    for (int p = 0; p < 8; p++) {
        A0[p] = 0ull; A1[p] = 0ull; A2[p] = 0ull; S[p] = 0ull; Q[p] = 0ull;
    }

#pragma unroll
    for (int ti = 0; ti < 16; ti++) {
        const float* yt = yb + (size_t)ti * 30 * NPIX;
        float v0 = (d0 >= 1)     ? yt[(size_t)(d0 - 1) * NPIX] : 0.f;
        float v1 = yt[(size_t)d0 * NPIX];
        float v2 = yt[(size_t)(d0 + 1) * NPIX];                    // d0+1 <= 28
        float v3 = yt[(size_t)(d0 + 2) * NPIX];                    // d0+2 <= 29
        float v4 = (d0 + 3 < 30) ? yt[(size_t)(d0 + 3) * NPIX] : 0.f;
        ull b0 = bc2(v0), b1 = bc2(v1), b2 = bc2(v2), b3 = bc2(v3), b4 = bc2(v4);
        const ulonglong2* w0 = (const ulonglong2*)(sw2 + (ti * 3 + 0) * 16);
        const ulonglong2* w1 = (const ulonglong2*)(sw2 + (ti * 3 + 1) * 16);
        const ulonglong2* w2 = (const ulonglong2*)(sw2 + (ti * 3 + 2) * 16);
#pragma unroll
        for (int p4 = 0; p4 < 4; p4++) {
            ulonglong2 a0 = w0[p4], a1 = w1[p4], a2 = w2[p4];
            FMA2(A0[2 * p4],     a0.x, b0); FMA2(A0[2 * p4 + 1], a0.y, b0);
            FMA2(A0[2 * p4],     a1.x, b1); FMA2(A0[2 * p4 + 1], a1.y, b1);
            FMA2(A0[2 * p4],     a2.x, b2); FMA2(A0[2 * p4 + 1], a2.y, b2);
            FMA2(A1[2 * p4],     a0.x, b1); FMA2(A1[2 * p4 + 1], a0.y, b1);
            FMA2(A1[2 * p4],     a1.x, b2); FMA2(A1[2 * p4 + 1], a1.y, b2);
            FMA2(A1[2 * p4],     a2.x, b3); FMA2(A1[2 * p4 + 1], a2.y, b3);
            FMA2(A2[2 * p4],     a0.x, b2); FMA2(A2[2 * p4 + 1], a0.y, b2);
            FMA2(A2[2 * p4],     a1.x, b3); FMA2(A2[2 * p4 + 1], a1.y, b3);
            FMA2(A2[2 * p4],     a2.x, b4); FMA2(A2[2 * p4 + 1], a2.y, b4);
        }
    }

#pragma unroll
    for (int dd = 0; dd < 3; dd++) {
        size_t ob = ((size_t)(b * 16) * 30 + (d0 + dd)) * NPIX + hw;
#pragma unroll
        for (int p = 0; p < 8; p++) {
            ull Av = (dd == 0) ? A0[p] : (dd == 1) ? A1[p] : A2[p];
            out[ob + (size_t)(2 * p)     * 30 * NPIX] = lo2(Av);
            out[ob + (size_t)(2 * p + 1) * 30 * NPIX] = hi2(Av);
            ADD2(S[p], Av);
            FMA2(Q[p], Av, Av);
        }
    }

#pragma unroll
    for (int p = 0; p < 8; p++) {
        float s0 = lo2(S[p]), s1 = hi2(S[p]);
        float q0 = lo2(Q[p]), q1 = hi2(Q[p]);
#pragma unroll
        for (int sh = 16; sh >= 1; sh >>= 1) {
            s0 += __shfl_down_sync(0xffffffffu, s0, sh);
            s1 += __shfl_down_sync(0xffffffffu, s1, sh);
            q0 += __shfl_down_sync(0xffffffffu, q0, sh);
            q1 += __shfl_down_sync(0xffffffffu, q1, sh);
        }
        if ((tid & 31) == 0) {
            atomicAdd(&bsum[2 * p],      s0);
            atomicAdd(&bsum[2 * p + 1],  s1);
            atomicAdd(&bsum[16 + 2 * p], q0);
            atomicAdd(&bsum[17 + 2 * p], q1);
        }
    }
    __syncthreads();
    if (tid < 32) atomicAdd(&g_sums[tid], bsum[tid]);
}

// ---------------- K4: BN stats + normalize + affine + relu (MLP=4, in place) ----
__global__ void k_bn(float* __restrict__ out, const float* __restrict__ bn_g,
                     const float* __restrict__ bn_b) {
    int base = blockIdx.x * 1024 + threadIdx.x;   // 960 blocks * 1024 f4 = 983040
    const float n = 245760.f;
    float4 v[4];
#pragma unroll
    for (int k = 0; k < 4; k++) v[k] = ((float4*)out)[base + k * 256];
#pragma unroll
    for (int k = 0; k < 4; k++) {
        int i4 = base + k * 256;
        int ch = (i4 / 30720) & 15;
        float mean = g_sums[ch] / n;
        float var = g_sums[16 + ch] / n - mean * mean;
        float inv = rsqrtf(var + 1e-5f);
        float gg = bn_g[ch] * inv;
        float bb = bn_b[ch] - mean * gg;
        v[k].x = fmaxf(v[k].x * gg + bb, 0.f);
        v[k].y = fmaxf(v[k].y * gg + bb, 0.f);
        v[k].z = fmaxf(v[k].z * gg + bb, 0.f);
        v[k].w = fmaxf(v[k].w * gg + bb, 0.f);
        ((float4*)out)[i4] = v[k];
    }
}

// ---------------- launch --------------------------------------------------------
extern "C" void kernel_launch(void* const* d_in, const int* in_sizes, int n_in,
                              void* d_out, int out_size) {
    const float* x      = (const float*)d_in[0];
    const float* p_w    = (const float*)d_in[1];
    const float* p_b    = (const float*)d_in[2];
    const float* m_w    = (const float*)d_in[3];
    const float* m_b    = (const float*)d_in[4];
    const float* conv_w = (const float*)d_in[5];
    const float* comp_w = (const float*)d_in[6];
    const float* spec_w = (const float*)d_in[7];
    const float* bn_g   = (const float*)d_in[8];
    const float* bn_b   = (const float*)d_in[9];
    float* out = (float*)d_out;

    const int SM_K = DTS * DTS * XSTR * 4 + 9 * 32 * 32 * 4 + 128;   // 223616
    cudaFuncSetAttribute(k_main, cudaFuncAttributeMaxDynamicSharedMemorySize, SM_K);

    k_prep<<<68, 256>>>(comp_w, conv_w, p_w, m_w);
    k_main<<<128, 512, SM_K>>>(x, p_b, m_b);
    k_spec<<<320, 256>>>(spec_w, out);
    k_bn<<<960, 256>>>(out, bn_g, bn_b);
    (void)in_sizes; (void)n_in; (void)out_size;
}

// round 16
// speedup vs baseline: 1.0020x; 1.0020x over previous
#include <cuda_runtime.h>
#include <math.h>

// Shapes: B=2, T=16, C=30, H=W=64.  NIMG = B*T = 32 images, NPIX = 4096.
// Deform conv input is the reshape-scrambled view xr[j][c'] with
//   f1 = j*30+c', b = f1/480, c = (f1%480)/16, t = f1%16  ->  x[b][t][c].
// Tiles are gathered directly from x.  conv1 (offset/mask) is fused into the
// deform kernel: one tile load serves both, om lives in thread-local memory.

#define NIMG 32
#define NPIX 4096
#define XSTR 36   // smem per-pixel stride (floats): 9 float4s -> all 8 bank groups hit.

typedef unsigned long long ull;

// packed-pair ops (sm_100a f32x2)
#define FMA2(d, a, b) asm("fma.rn.f32x2 %0, %1, %2, %0;" : "+l"(d) : "l"(a), "l"(b))
#define MUL2(d, a, b) asm("mul.rn.f32x2 %0, %1, %2;" : "=l"(d) : "l"(a), "l"(b))
#define ADD2(d, a)    asm("add.rn.f32x2 %0, %0, %1;" : "+l"(d) : "l"(a))

__device__ __forceinline__ ull bc2(float x) {
    ull r;
    asm("mov.b64 %0, {%1, %1};" : "=l"(r) : "r"(__float_as_uint(x)));
    return r;
}
__device__ __forceinline__ ull pk2(float lo, float hi) {
    ull r;
    asm("mov.b64 %0, {%1, %2};" : "=l"(r) : "r"(__float_as_uint(lo)), "r"(__float_as_uint(hi)));
    return r;
}
__device__ __forceinline__ float lo2(ull v) { return __uint_as_float((unsigned)v); }
__device__ __forceinline__ float hi2(ull v) { return __uint_as_float((unsigned)(v >> 32)); }

// plane offset of scrambled channel cp for image j:  x[b][t][c] plane base
__device__ __forceinline__ int plane_off(int j, int cp) {
    int f1 = j * 30 + cp;
    int b = (f1 >= 480) ? 1 : 0;
    int rem = f1 - b * 480;
    int c = rem >> 4;
    int tt = rem & 15;
    return ((b * 16 + tt) * 30 + c) * NPIX;
}

// ---------------- scratch (device globals; no runtime allocation) -------------
__device__ float g_y1[NIMG * 30 * NPIX];                   // deform+comp output
// packed weights: rows indexed by absolute channel c, outputs consecutive (pairs)
__device__ __align__(16) float g_Wc2[9 * 32 * 32];         // [tap][c][o] o-padded to 32
__device__ __align__(16) float g_Wk2[9 * 32 * 28];         // [tap][c][o] o-padded to 28
__device__ float g_sums[32];                               // BN sum / sumsq per channel

// ---------------- K0: weight prep + zero stats --------------------------------
__global__ void k_prep(const float* __restrict__ comp_w, const float* __restrict__ conv_w,
                       const float* __restrict__ p_w, const float* __restrict__ m_w) {
    int t = blockIdx.x * blockDim.x + threadIdx.x;
    const int NW2C = 9 * 32 * 32;          // 9216
    const int NW2K = 9 * 32 * 28;          // 8064
    if (t < NW2C) {
        int n = t >> 10;
        int r = t & 1023;
        int c = r >> 5;
        int o = r & 31;
        float acc = 0.f;
        if (c < 30 && o < 30) {
            for (int m = 0; m < 90; m++)
                acc += comp_w[o * 90 + m] * conv_w[(m * 30 + c) * 9 + n];
        }
        g_Wc2[t] = acc;
    } else if (t < NW2C + NW2K) {
        int u = t - NW2C;
        int n = u / 896;
        int r = u - n * 896;
        int c = r / 28;
        int o = r - c * 28;
        float v = 0.f;
        if (c < 30) {
            if (o < 18)      v = p_w[(o * 30 + c) * 9 + n];
            else if (o < 27) v = m_w[((o - 18) * 30 + c) * 9 + n];
        }
        g_Wk2[u] = v;
    } else if (t < NW2C + NW2K + 32) {
        g_sums[t - (NW2C + NW2K)] = 0.f;
    }
}

// ---------------- K1: FUSED offset/mask conv + deform sample + matvec -----------
#define DTS 36
// cold path: gather corner channels straight from scrambled x, packed accumulate.
// Channels >=30 load via po[]=0 (finite garbage) and are killed by zero weights.
__device__ __forceinline__ void add_corner_x2(ull* s, const float* __restrict__ x,
                                              const int* po, int qx, int qy,
                                              ull g2, int co) {
    if (qx >= 1 && qx <= 64 && qy >= 1 && qy <= 64) {
        int hw = (qx - 1) * 64 + (qy - 1);
#pragma unroll
        for (int u = 0; u < 8; u++) {
            int c0 = co + 2 * u;
            ull v = pk2(x[po[c0] + hw], x[po[c0 + 1] + hw]);
            FMA2(s[u], v, g2);
        }
    }
}

__global__ void __launch_bounds__(512, 1) k_main(const float* __restrict__ x,
                                                 const float* __restrict__ p_b,
                                                 const float* __restrict__ m_b) {
    extern __shared__ float sm[];
    float* xt = sm;                        // [DTS*DTS*XSTR] = 186624 B
    float* wt = sm + DTS * DTS * XSTR;     // max(9*32*28, 9*32*32) = 36864 B
    int* po = (int*)(wt + 9 * 32 * 32);    // [32]
    int blk = blockIdx.x;
    int j = blk >> 2;
    int tile = blk & 3;
    int th0 = (tile >> 1) << 5;
    int tw0 = (tile & 1) << 5;
    int tx0 = th0 - 1;   // padded coord of smem row 0
    int ty0 = tw0 - 1;
    int tid = threadIdx.x;

    if (tid < 32) po[tid] = (tid < 30) ? plane_off(j, tid) : 0;
    __syncthreads();

    // ---- shared tile load (serves both conv phases) ----
    for (int pos = tid; pos < DTS * DTS; pos += 512) {
        int rr = pos / DTS, cc = pos % DTS;
        int qx = tx0 + rr, qy = ty0 + cc;
        float v[32];
        if (qx >= 1 && qx <= 64 && qy >= 1 && qy <= 64) {
            int hw = (qx - 1) * 64 + (qy - 1);
#pragma unroll
            for (int cp = 0; cp < 30; cp++) v[cp] = x[po[cp] + hw];
        } else {
#pragma unroll
            for (int cp = 0; cp < 30; cp++) v[cp] = 0.f;
        }
        v[30] = 0.f; v[31] = 0.f;
        float4* d = (float4*)(xt + pos * XSTR);
#pragma unroll
        for (int q = 0; q < 8; q++)
            d[q] = make_float4(v[4 * q], v[4 * q + 1], v[4 * q + 2], v[4 * q + 3]);
    }
    // conv1 weights first
    for (int p = tid; p < 9 * 32 * 28 / 4; p += 512)
        ((float4*)wt)[p] = ((const float4*)g_Wk2)[p];
    __syncthreads();

    int tx = tid & 31, ty = tid >> 5;      // ty 0..15
    int h0 = th0 + ty, h1 = h0 + 16;
    int w = tw0 + tx;

    // ================= phase 1: offset/mask conv (27 outs, 2 px) =================
    float om0[27], om1[27];   // runtime-indexed later -> local memory (by design)
    {
        ull A0[14], A1[14];
#pragma unroll
        for (int op = 0; op < 14; op++) { A0[op] = 0ull; A1[op] = 0ull; }

        for (int n = 0; n < 9; n++) {
            int i = n / 3;
            int jj = n - i * 3;
            // unpadded (h-1+i, w-1+jj) -> xt row ty+i+1, col tx+jj+1
            const float* b0 = xt + ((ty + i + 1) * DTS + (tx + jj + 1)) * XSTR;
            const float* b1 = b0 + 16 * DTS * XSTR;
            const float* wn = wt + n * 32 * 28;
#pragma unroll
            for (int half = 0; half < 2; half++) {
                int co = half << 4;
                float4 sA[4], sB[4];
                const float4* p0 = (const float4*)(b0 + co);
                const float4* p1 = (const float4*)(b1 + co);
#pragma unroll
                for (int q = 0; q < 4; q++) { sA[q] = p0[q]; sB[q] = p1[q]; }
#pragma unroll
                for (int i4 = 0; i4 < 4; i4++) {
                    float4 va = sA[i4], vb = sB[i4];
#pragma unroll
                    for (int comp = 0; comp < 4; comp++) {
                        float fa = comp == 0 ? va.x : comp == 1 ? va.y : comp == 2 ? va.z : va.w;
                        float fb = comp == 0 ? vb.x : comp == 1 ? vb.y : comp == 2 ? vb.z : vb.w;
                        int c = co + (i4 << 2) + comp;
                        ull ba = bc2(fa), bb = bc2(fb);
                        const ulonglong2* wc2 = (const ulonglong2*)(wn + c * 28);
#pragma unroll
                        for (int k = 0; k < 7; k++) {
                            ulonglong2 wv = wc2[k];
                            FMA2(A0[2 * k],     wv.x, ba);
                            FMA2(A0[2 * k + 1], wv.y, ba);
                            FMA2(A1[2 * k],     wv.x, bb);
                            FMA2(A1[2 * k + 1], wv.y, bb);
                        }
                    }
                }
            }
        }
#pragma unroll
        for (int o = 0; o < 18; o++) {
            float bo = p_b[o];
            om0[o] = ((o & 1) ? hi2(A0[o >> 1]) : lo2(A0[o >> 1])) + bo;
            om1[o] = ((o & 1) ? hi2(A1[o >> 1]) : lo2(A1[o >> 1])) + bo;
        }
#pragma unroll
        for (int o = 18; o < 27; o++) {
            float bo = m_b[o - 18];
            float z0 = ((o & 1) ? hi2(A0[o >> 1]) : lo2(A0[o >> 1])) + bo;
            float z1 = ((o & 1) ? hi2(A1[o >> 1]) : lo2(A1[o >> 1])) + bo;
            om0[o] = 1.f / (1.f + expf(-z0));
            om1[o] = 1.f / (1.f + expf(-z1));
        }
    }

    // swap in deform weights (Wk2 region is dead)
    __syncthreads();
    for (int p = tid; p < 9 * 32 * 32 / 4; p += 512)
        ((float4*)wt)[p] = ((const float4*)g_Wc2)[p];
    __syncthreads();

    // ================= phase 2: deform sample + matvec (packed blend) ============
    ull A0[15], A1[15];
#pragma unroll
    for (int op = 0; op < 15; op++) { A0[op] = 0ull; A1[op] = 0ull; }

    for (int n = 0; n < 9; n++) {
        int dxi = n / 3;
        int dyi = n - dxi * 3;
        const float* wn = wt + n * 32 * 32;

        // ---- pixel 0 geometry ----
        float ox0 = om0[n];
        float oy0 = om0[9 + n];
        float mk0 = om0[18 + n];
        float px0 = (float)(h0 + dxi) + ox0;
        float py0 = (float)(w + dyi) + oy0;
        float qfx0 = floorf(px0), qfy0 = floorf(py0);
        float lx0 = fminf(fmaxf(qfx0, 0.f), 65.f);
        float ly0 = fminf(fmaxf(qfy0, 0.f), 65.f);
        float rx0 = fminf(fmaxf(qfx0 + 1.f, 0.f), 65.f);
        float ry0 = fminf(fmaxf(qfy0 + 1.f, 0.f), 65.f);
        float pxc0 = fminf(fmaxf(px0, 0.f), 65.f);
        float pyc0 = fminf(fmaxf(py0, 0.f), 65.f);
        float gxl0 = 1.f + lx0 - pxc0, gxr0 = 1.f - rx0 + pxc0;
        float gyl0 = 1.f + ly0 - pyc0, gyr0 = 1.f - ry0 + pyc0;
        ull g0lt = bc2(gxl0 * gyl0 * mk0), g0rb = bc2(gxr0 * gyr0 * mk0);
        ull g0lb = bc2(gxl0 * gyr0 * mk0), g0rt = bc2(gxr0 * gyl0 * mk0);
        int a0x = (int)lx0, a0y = (int)ly0, b0x = (int)rx0, b0y = (int)ry0;
        bool f0 = (a0x >= tx0) & (b0x < tx0 + DTS) & (a0y >= ty0) & (b0y < ty0 + DTS);

        // ---- pixel 1 geometry ----
        float ox1 = om1[n];
        float oy1 = om1[9 + n];
        float mk1 = om1[18 + n];
        float px1 = (float)(h1 + dxi) + ox1;
        float py1 = (float)(w + dyi) + oy1;
        float qfx1 = floorf(px1), qfy1 = floorf(py1);
        float lx1 = fminf(fmaxf(qfx1, 0.f), 65.f);
        float ly1 = fminf(fmaxf(qfy1, 0.f), 65.f);
        float rx1 = fminf(fmaxf(qfx1 + 1.f, 0.f), 65.f);
        float ry1 = fminf(fmaxf(qfy1 + 1.f, 0.f), 65.f);
        float pxc1 = fminf(fmaxf(px1, 0.f), 65.f);
        float pyc1 = fminf(fmaxf(py1, 0.f), 65.f);
        float gxl1 = 1.f + lx1 - pxc1, gxr1 = 1.f - rx1 + pxc1;
        float gyl1 = 1.f + ly1 - pyc1, gyr1 = 1.f - ry1 + pyc1;
        ull g1lt = bc2(gxl1 * gyl1 * mk1), g1rb = bc2(gxr1 * gyr1 * mk1);
        ull g1lb = bc2(gxl1 * gyr1 * mk1), g1rt = bc2(gxr1 * gyl1 * mk1);
        int a1x = (int)lx1, a1y = (int)ly1, b1x = (int)rx1, b1y = (int)ry1;
        bool f1 = (a1x >= tx0) & (b1x < tx0 + DTS) & (a1y >= ty0) & (b1y < ty0 + DTS);

#pragma unroll
        for (int half = 0; half < 2; half++) {
            int co = half << 4;
            ull s2A[8], s2B[8];

            if (f0) {
                const ulonglong2* A = (const ulonglong2*)(xt + ((a0x - tx0) * DTS + (a0y - ty0)) * XSTR + co);
                const ulonglong2* B = (const ulonglong2*)(xt + ((b0x - tx0) * DTS + (b0y - ty0)) * XSTR + co);
                const ulonglong2* C = (const ulonglong2*)(xt + ((a0x - tx0) * DTS + (b0y - ty0)) * XSTR + co);
                const ulonglong2* D = (const ulonglong2*)(xt + ((b0x - tx0) * DTS + (a0y - ty0)) * XSTR + co);
#pragma unroll
                for (int q = 0; q < 4; q++) {
                    ulonglong2 a = A[q], b = B[q], c = C[q], d = D[q];
                    MUL2(s2A[2 * q],     a.x, g0lt);
                    FMA2(s2A[2 * q],     b.x, g0rb);
                    FMA2(s2A[2 * q],     c.x, g0lb);
                    FMA2(s2A[2 * q],     d.x, g0rt);
                    MUL2(s2A[2 * q + 1], a.y, g0lt);
                    FMA2(s2A[2 * q + 1], b.y, g0rb);
                    FMA2(s2A[2 * q + 1], c.y, g0lb);
                    FMA2(s2A[2 * q + 1], d.y, g0rt);
                }
            } else {
#pragma unroll
                for (int u = 0; u < 8; u++) s2A[u] = 0ull;
                add_corner_x2(s2A, x, po, a0x, a0y, g0lt, co);
                add_corner_x2(s2A, x, po, b0x, b0y, g0rb, co);
                add_corner_x2(s2A, x, po, a0x, b0y, g0lb, co);
                add_corner_x2(s2A, x, po, b0x, a0y, g0rt, co);
            }

            if (f1) {
                const ulonglong2* A = (const ulonglong2*)(xt + ((a1x - tx0) * DTS + (a1y - ty0)) * XSTR + co);
                const ulonglong2* B = (const ulonglong2*)(xt + ((b1x - tx0) * DTS + (b1y - ty0)) * XSTR + co);
                const ulonglong2* C = (const ulonglong2*)(xt + ((a1x - tx0) * DTS + (b1y - ty0)) * XSTR + co);
                const ulonglong2* D = (const ulonglong2*)(xt + ((b1x - tx0) * DTS + (a1y - ty0)) * XSTR + co);
#pragma unroll
                for (int q = 0; q < 4; q++) {
                    ulonglong2 a = A[q], b = B[q], c = C[q], d = D[q];
                    MUL2(s2B[2 * q],     a.x, g1lt);
                    FMA2(s2B[2 * q],     b.x, g1rb);
                    FMA2(s2B[2 * q],     c.x, g1lb);
                    FMA2(s2B[2 * q],     d.x, g1rt);
                    MUL2(s2B[2 * q + 1], a.y, g1lt);
                    FMA2(s2B[2 * q + 1], b.y, g1rb);
                    FMA2(s2B[2 * q + 1], c.y, g1lb);
                    FMA2(s2B[2 * q + 1], d.y, g1rt);
                }
            } else {
#pragma unroll
                for (int u = 0; u < 8; u++) s2B[u] = 0ull;
                add_corner_x2(s2B, x, po, a1x, a1y, g1lt, co);
                add_corner_x2(s2B, x, po, b1x, b1y, g1rb, co);
                add_corner_x2(s2B, x, po, a1x, b1y, g1lb, co);
                add_corner_x2(s2B, x, po, b1x, a1y, g1rt, co);
            }

#pragma unroll
            for (int u = 0; u < 8; u++) {
#pragma unroll
                for (int half2 = 0; half2 < 2; half2++) {
                    int c = co + 2 * u + half2;
                    float fa = half2 ? hi2(s2A[u]) : lo2(s2A[u]);
                    float fb = half2 ? hi2(s2B[u]) : lo2(s2B[u]);
                    ull ba = bc2(fa), bb = bc2(fb);
                    const float* wrow = wn + c * 32;
                    const ulonglong2* wc2 = (const ulonglong2*)wrow;
#pragma unroll
                    for (int k = 0; k < 7; k++) {
                        ulonglong2 wv = wc2[k];
                        FMA2(A0[2 * k],     wv.x, ba);
                        FMA2(A0[2 * k + 1], wv.y, ba);
                        FMA2(A1[2 * k],     wv.x, bb);
                        FMA2(A1[2 * k + 1], wv.y, bb);
                    }
                    ull w14 = *(const ull*)(wrow + 28);   // pair (o=28,29)
                    FMA2(A0[14], w14, ba);
                    FMA2(A1[14], w14, bb);
                }
            }
        }
    }

    int hw0 = h0 * 64 + w;
    float* yb0 = g_y1 + (size_t)j * 30 * NPIX + hw0;
    float* yb1 = yb0 + 16 * 64;
#pragma unroll
    for (int op = 0; op < 15; op++) {
        yb0[(size_t)(2 * op)     * NPIX] = lo2(A0[op]);
        yb0[(size_t)(2 * op + 1) * NPIX] = hi2(A0[op]);
        yb1[(size_t)(2 * op)     * NPIX] = lo2(A1[op]);
        yb1[(size_t)(2 * op + 1) * NPIX] = hi2(A1[op]);
    }
}

// ---------------- K3: spec conv, 3 d-outputs/thread, immediate-consume window ---
__global__ void __launch_bounds__(256) k_spec(const float* __restrict__ spec_w,
                                              float* __restrict__ out) {
    __shared__ float sw2[48 * 16];   // transposed: [c=ti*3+kd][to]
    __shared__ float bsum[32];
    int tid = threadIdx.x;
    for (int p = tid; p < 768; p += 256) {
        int to = p / 48, c = p - to * 48;
        sw2[c * 16 + to] = spec_w[p];
    }
    if (tid < 32) bsum[tid] = 0.f;
    __syncthreads();

    int bx = blockIdx.x;             // 320 = 2 b * 10 dchunk * 16 hw-blocks
    int b  = bx / 160;
    int r  = bx - b * 160;
    int dc = r >> 4;                 // 0..9
    int hw = ((r & 15) << 8) + tid;
    int d0 = dc * 3;                 // 0,3,...,27

    const float* yb = g_y1 + (size_t)b * 16 * 30 * NPIX + hw;

    ull A0[8], A1[8], A2[8], S[8], Q[8];
#pragma unroll
    for (int p = 0; p < 8; p++) {
        A0[p] = 0ull; A1[p] = 0ull; A2[p] = 0ull; S[p] = 0ull; Q[p] = 0ull;
    }

#pragma unroll
    for (int ti = 0; ti < 16; ti++) {
        const float* yt = yb + (size_t)ti * 30 * NPIX;
        float v0 = (d0 >= 1)     ? yt[(size_t)(d0 - 1) * NPIX] : 0.f;
        float v1 = yt[(size_t)d0 * NPIX];
        float v2 = yt[(size_t)(d0 + 1) * NPIX];                    // d0+1 <= 28
        float v3 = yt[(size_t)(d0 + 2) * NPIX];                    // d0+2 <= 29
        float v4 = (d0 + 3 < 30) ? yt[(size_t)(d0 + 3) * NPIX] : 0.f;
        ull b0 = bc2(v0), b1 = bc2(v1), b2 = bc2(v2), b3 = bc2(v3), b4 = bc2(v4);
        const ulonglong2* w0 = (const ulonglong2*)(sw2 + (ti * 3 + 0) * 16);
        const ulonglong2* w1 = (const ulonglong2*)(sw2 + (ti * 3 + 1) * 16);
        const ulonglong2* w2 = (const ulonglong2*)(sw2 + (ti * 3 + 2) * 16);
#pragma unroll
        for (int p4 = 0; p4 < 4; p4++) {
            ulonglong2 a0 = w0[p4], a1 = w1[p4], a2 = w2[p4];
            FMA2(A0[2 * p4],     a0.x, b0); FMA2(A0[2 * p4 + 1], a0.y, b0);
            FMA2(A0[2 * p4],     a1.x, b1); FMA2(A0[2 * p4 + 1], a1.y, b1);
            FMA2(A0[2 * p4],     a2.x, b2); FMA2(A0[2 * p4 + 1], a2.y, b2);
            FMA2(A1[2 * p4],     a0.x, b1); FMA2(A1[2 * p4 + 1], a0.y, b1);
            FMA2(A1[2 * p4],     a1.x, b2); FMA2(A1[2 * p4 + 1], a1.y, b2);
            FMA2(A1[2 * p4],     a2.x, b3); FMA2(A1[2 * p4 + 1], a2.y, b3);
            FMA2(A2[2 * p4],     a0.x, b2); FMA2(A2[2 * p4 + 1], a0.y, b2);
            FMA2(A2[2 * p4],     a1.x, b3); FMA2(A2[2 * p4 + 1], a1.y, b3);
            FMA2(A2[2 * p4],     a2.x, b4); FMA2(A2[2 * p4 + 1], a2.y, b4);
        }
    }

#pragma unroll
    for (int dd = 0; dd < 3; dd++) {
        size_t ob = ((size_t)(b * 16) * 30 + (d0 + dd)) * NPIX + hw;
#pragma unroll
        for (int p = 0; p < 8; p++) {
            ull Av = (dd == 0) ? A0[p] : (dd == 1) ? A1[p] : A2[p];
            out[ob + (size_t)(2 * p)     * 30 * NPIX] = lo2(Av);
            out[ob + (size_t)(2 * p + 1) * 30 * NPIX] = hi2(Av);
            ADD2(S[p], Av);
            FMA2(Q[p], Av, Av);
        }
    }

#pragma unroll
    for (int p = 0; p < 8; p++) {
        float s0 = lo2(S[p]), s1 = hi2(S[p]);
        float q0 = lo2(Q[p]), q1 = hi2(Q[p]);
#pragma unroll
        for (int sh = 16; sh >= 1; sh >>= 1) {
            s0 += __shfl_down_sync(0xffffffffu, s0, sh);
            s1 += __shfl_down_sync(0xffffffffu, s1, sh);
            q0 += __shfl_down_sync(0xffffffffu, q0, sh);
            q1 += __shfl_down_sync(0xffffffffu, q1, sh);
        }
        if ((tid & 31) == 0) {
            atomicAdd(&bsum[2 * p],      s0);
            atomicAdd(&bsum[2 * p + 1],  s1);
            atomicAdd(&bsum[16 + 2 * p], q0);
            atomicAdd(&bsum[17 + 2 * p], q1);
        }
    }
    __syncthreads();
    if (tid < 32) atomicAdd(&g_sums[tid], bsum[tid]);
}

// ---------------- K4: BN stats + normalize + affine + relu (fused, in place) ----
__global__ void k_bn(float* __restrict__ out, const float* __restrict__ bn_g,
                     const float* __restrict__ bn_b) {
    int i4 = blockIdx.x * 256 + threadIdx.x;   // < 983040 float4s
    int ch = (i4 / 30720) & 15;
    const float n = 245760.f;
    float mean = g_sums[ch] / n;
    float var = g_sums[16 + ch] / n - mean * mean;
    float inv = rsqrtf(var + 1e-5f);
    float gg = bn_g[ch] * inv;
    float bb = bn_b[ch] - mean * gg;
    float4 v = ((float4*)out)[i4];
    v.x = fmaxf(v.x * gg + bb, 0.f);
    v.y = fmaxf(v.y * gg + bb, 0.f);
    v.z = fmaxf(v.z * gg + bb, 0.f);
    v.w = fmaxf(v.w * gg + bb, 0.f);
    ((float4*)out)[i4] = v;
}

// ---------------- launch --------------------------------------------------------
extern "C" void kernel_launch(void* const* d_in, const int* in_sizes, int n_in,
                              void* d_out, int out_size) {
    const float* x      = (const float*)d_in[0];
    const float* p_w    = (const float*)d_in[1];
    const float* p_b    = (const float*)d_in[2];
    const float* m_w    = (const float*)d_in[3];
    const float* m_b    = (const float*)d_in[4];
    const float* conv_w = (const float*)d_in[5];
    const float* comp_w = (const float*)d_in[6];
    const float* spec_w = (const float*)d_in[7];
    const float* bn_g   = (const float*)d_in[8];
    const float* bn_b   = (const float*)d_in[9];
    float* out = (float*)d_out;

    const int SM_K = DTS * DTS * XSTR * 4 + 9 * 32 * 32 * 4 + 128;   // 223616
    cudaFuncSetAttribute(k_main, cudaFuncAttributeMaxDynamicSharedMemorySize, SM_K);

    k_prep<<<68, 256>>>(comp_w, conv_w, p_w, m_w);
    k_main<<<128, 512, SM_K>>>(x, p_b, m_b);
    k_spec<<<320, 256>>>(spec_w, out);
    k_bn<<<3840, 256>>>(out, bn_g, bn_b);
    (void)in_sizes; (void)n_in; (void)out_size;
}

// round 17
// speedup vs baseline: 1.2018x; 1.1994x over previous
#include <cuda_runtime.h>
#include <math.h>

// Shapes: B=2, T=16, C=30, H=W=64.  NIMG = B*T = 32 images, NPIX = 4096.
// Deform conv input is the reshape-scrambled view xr[j][c'] with
//   f1 = j*30+c', b = f1/480, c = (f1%480)/16, t = f1%16  ->  x[b][t][c].
// Tiles are gathered directly from x.  conv1 (offset/mask) is fused into the
// deform kernel.  Phase-2 weights live in __constant__ (LDCU port, off the LSU).

#define NIMG 32
#define NPIX 4096
#define XSTR 36   // smem per-pixel stride (floats): 9 float4s -> all 8 bank groups hit.

typedef unsigned long long ull;

// packed-pair ops (sm_100a f32x2)
#define FMA2(d, a, b) asm("fma.rn.f32x2 %0, %1, %2, %0;" : "+l"(d) : "l"(a), "l"(b))
#define MUL2(d, a, b) asm("mul.rn.f32x2 %0, %1, %2;" : "=l"(d) : "l"(a), "l"(b))
#define ADD2(d, a)    asm("add.rn.f32x2 %0, %0, %1;" : "+l"(d) : "l"(a))

__device__ __forceinline__ ull bc2(float x) {
    ull r;
    asm("mov.b64 %0, {%1, %1};" : "=l"(r) : "r"(__float_as_uint(x)));
    return r;
}
__device__ __forceinline__ ull pk2(float lo, float hi) {
    ull r;
    asm("mov.b64 %0, {%1, %2};" : "=l"(r) : "r"(__float_as_uint(lo)), "r"(__float_as_uint(hi)));
    return r;
}
__device__ __forceinline__ float lo2(ull v) { return __uint_as_float((unsigned)v); }
__device__ __forceinline__ float hi2(ull v) { return __uint_as_float((unsigned)(v >> 32)); }

// plane offset of scrambled channel cp for image j:  x[b][t][c] plane base
__device__ __forceinline__ int plane_off(int j, int cp) {
    int f1 = j * 30 + cp;
    int b = (f1 >= 480) ? 1 : 0;
    int rem = f1 - b * 480;
    int c = rem >> 4;
    int tt = rem & 15;
    return ((b * 16 + tt) * 30 + c) * NPIX;
}

// ---------------- scratch (device globals; no runtime allocation) -------------
__device__ float g_y1[NIMG * 30 * NPIX];                   // deform+comp output
__device__ __align__(16) float g_Wc2[9 * 32 * 32];         // staging for c_Wc2
__device__ __align__(16) float g_Wk2[9 * 32 * 28];         // [tap][c][o] o-padded to 28
__device__ float g_sums[32];                               // BN sum / sumsq per channel
__constant__ __align__(16) float c_Wc2[9 * 32 * 32];       // phase-2 weights (36.9 KB)

// ---------------- K0: weight prep + zero stats --------------------------------
__global__ void k_prep(const float* __restrict__ comp_w, const float* __restrict__ conv_w,
                       const float* __restrict__ p_w, const float* __restrict__ m_w) {
    int t = blockIdx.x * blockDim.x + threadIdx.x;
    const int NW2C = 9 * 32 * 32;          // 9216
    const int NW2K = 9 * 32 * 28;          // 8064
    if (t < NW2C) {
        int n = t >> 10;
        int r = t & 1023;
        int c = r >> 5;
        int o = r & 31;
        float acc = 0.f;
        if (c < 30 && o < 30) {
            for (int m = 0; m < 90; m++)
                acc += comp_w[o * 90 + m] * conv_w[(m * 30 + c) * 9 + n];
        }
        g_Wc2[t] = acc;
    } else if (t < NW2C + NW2K) {
        int u = t - NW2C;
        int n = u / 896;
        int r = u - n * 896;
        int c = r / 28;
        int o = r - c * 28;
        float v = 0.f;
        if (c < 30) {
            if (o < 18)      v = p_w[(o * 30 + c) * 9 + n];
            else if (o < 27) v = m_w[((o - 18) * 30 + c) * 9 + n];
        }
        g_Wk2[u] = v;
    } else if (t < NW2C + NW2K + 32) {
        g_sums[t - (NW2C + NW2K)] = 0.f;
    }
}

// ---------------- K1: FUSED offset/mask conv + deform sample + matvec -----------
#define DTS 36
// cold path: gather corner channels straight from scrambled x, packed accumulate.
// Channels >=30 load via po[]=0 (finite garbage) and are killed by zero weights.
__device__ __forceinline__ void add_corner_x2(ull* s, const float* __restrict__ x,
                                              const int* po, int qx, int qy,
                                              ull g2, int co) {
    if (qx >= 1 && qx <= 64 && qy >= 1 && qy <= 64) {
        int hw = (qx - 1) * 64 + (qy - 1);
#pragma unroll
        for (int u = 0; u < 8; u++) {
            int c0 = co + 2 * u;
            ull v = pk2(x[po[c0] + hw], x[po[c0 + 1] + hw]);
            FMA2(s[u], v, g2);
        }
    }
}

__global__ void __launch_bounds__(512, 1) k_main(const float* __restrict__ x,
                                                 const float* __restrict__ p_b,
                                                 const float* __restrict__ m_b) {
    extern __shared__ float sm[];
    float* xt = sm;                        // [DTS*DTS*XSTR] = 186624 B
    float* wt = sm + DTS * DTS * XSTR;     // [9*32*28] = 32256 B (Wk2 only)
    int* po = (int*)(wt + 9 * 32 * 28);    // [32]
    int blk = blockIdx.x;
    int j = blk >> 2;
    int tile = blk & 3;
    int th0 = (tile >> 1) << 5;
    int tw0 = (tile & 1) << 5;
    int tx0 = th0 - 1;   // padded coord of smem row 0
    int ty0 = tw0 - 1;
    int tid = threadIdx.x;

    if (tid < 32) po[tid] = (tid < 30) ? plane_off(j, tid) : 0;
    __syncthreads();

    // ---- shared tile load (serves both conv phases) ----
    for (int pos = tid; pos < DTS * DTS; pos += 512) {
        int rr = pos / DTS, cc = pos % DTS;
        int qx = tx0 + rr, qy = ty0 + cc;
        float v[32];
        if (qx >= 1 && qx <= 64 && qy >= 1 && qy <= 64) {
            int hw = (qx - 1) * 64 + (qy - 1);
#pragma unroll
            for (int cp = 0; cp < 30; cp++) v[cp] = x[po[cp] + hw];
        } else {
#pragma unroll
            for (int cp = 0; cp < 30; cp++) v[cp] = 0.f;
        }
        v[30] = 0.f; v[31] = 0.f;
        float4* d = (float4*)(xt + pos * XSTR);
#pragma unroll
        for (int q = 0; q < 8; q++)
            d[q] = make_float4(v[4 * q], v[4 * q + 1], v[4 * q + 2], v[4 * q + 3]);
    }
    for (int p = tid; p < 9 * 32 * 28 / 4; p += 512)
        ((float4*)wt)[p] = ((const float4*)g_Wk2)[p];
    __syncthreads();

    int tx = tid & 31, ty = tid >> 5;      // ty 0..15
    int h0 = th0 + ty, h1 = h0 + 16;
    int w = tw0 + tx;

    // ================= phase 1: offset/mask conv (27 outs, 2 px) =================
    float om0[27], om1[27];   // runtime-indexed later -> local memory (by design)
    {
        ull A0[14], A1[14];
#pragma unroll
        for (int op = 0; op < 14; op++) { A0[op] = 0ull; A1[op] = 0ull; }

        for (int n = 0; n < 9; n++) {
            int i = n / 3;
            int jj = n - i * 3;
            // unpadded (h-1+i, w-1+jj) -> xt row ty+i+1, col tx+jj+1
            const float* b0 = xt + ((ty + i + 1) * DTS + (tx + jj + 1)) * XSTR;
            const float* b1 = b0 + 16 * DTS * XSTR;
            const float* wn = wt + n * 32 * 28;
#pragma unroll
            for (int half = 0; half < 2; half++) {
                int co = half << 4;
                float4 sA[4], sB[4];
                const float4* p0 = (const float4*)(b0 + co);
                const float4* p1 = (const float4*)(b1 + co);
#pragma unroll
                for (int q = 0; q < 4; q++) { sA[q] = p0[q]; sB[q] = p1[q]; }
#pragma unroll
                for (int i4 = 0; i4 < 4; i4++) {
                    float4 va = sA[i4], vb = sB[i4];
#pragma unroll
                    for (int comp = 0; comp < 4; comp++) {
                        float fa = comp == 0 ? va.x : comp == 1 ? va.y : comp == 2 ? va.z : va.w;
                        float fb = comp == 0 ? vb.x : comp == 1 ? vb.y : comp == 2 ? vb.z : vb.w;
                        int c = co + (i4 << 2) + comp;
                        ull ba = bc2(fa), bb = bc2(fb);
                        const ulonglong2* wc2 = (const ulonglong2*)(wn + c * 28);
#pragma unroll
                        for (int k = 0; k < 7; k++) {
                            ulonglong2 wv = wc2[k];
                            FMA2(A0[2 * k],     wv.x, ba);
                            FMA2(A0[2 * k + 1], wv.y, ba);
                            FMA2(A1[2 * k],     wv.x, bb);
                            FMA2(A1[2 * k + 1], wv.y, bb);
                        }
                    }
                }
            }
        }
#pragma unroll
        for (int o = 0; o < 18; o++) {
            float bo = p_b[o];
            om0[o] = ((o & 1) ? hi2(A0[o >> 1]) : lo2(A0[o >> 1])) + bo;
            om1[o] = ((o & 1) ? hi2(A1[o >> 1]) : lo2(A1[o >> 1])) + bo;
        }
#pragma unroll
        for (int o = 18; o < 27; o++) {
            float bo = m_b[o - 18];
            float z0 = ((o & 1) ? hi2(A0[o >> 1]) : lo2(A0[o >> 1])) + bo;
            float z1 = ((o & 1) ? hi2(A1[o >> 1]) : lo2(A1[o >> 1])) + bo;
            om0[o] = 1.f / (1.f + expf(-z0));
            om1[o] = 1.f / (1.f + expf(-z1));
        }
    }
    // no sync needed: phase 2 reads xt (unchanged) and constant weights.

    // ================= phase 2: deform sample + matvec (const weights) ===========
    ull A0[15], A1[15];
#pragma unroll
    for (int op = 0; op < 15; op++) { A0[op] = 0ull; A1[op] = 0ull; }

    for (int n = 0; n < 9; n++) {
        int dxi = n / 3;
        int dyi = n - dxi * 3;

        // ---- pixel 0 geometry ----
        float ox0 = om0[n];
        float oy0 = om0[9 + n];
        float mk0 = om0[18 + n];
        float px0 = (float)(h0 + dxi) + ox0;
        float py0 = (float)(w + dyi) + oy0;
        float qfx0 = floorf(px0), qfy0 = floorf(py0);
        float lx0 = fminf(fmaxf(qfx0, 0.f), 65.f);
        float ly0 = fminf(fmaxf(qfy0, 0.f), 65.f);
        float rx0 = fminf(fmaxf(qfx0 + 1.f, 0.f), 65.f);
        float ry0 = fminf(fmaxf(qfy0 + 1.f, 0.f), 65.f);
        float pxc0 = fminf(fmaxf(px0, 0.f), 65.f);
        float pyc0 = fminf(fmaxf(py0, 0.f), 65.f);
        float gxl0 = 1.f + lx0 - pxc0, gxr0 = 1.f - rx0 + pxc0;
        float gyl0 = 1.f + ly0 - pyc0, gyr0 = 1.f - ry0 + pyc0;
        ull g0lt = bc2(gxl0 * gyl0 * mk0), g0rb = bc2(gxr0 * gyr0 * mk0);
        ull g0lb = bc2(gxl0 * gyr0 * mk0), g0rt = bc2(gxr0 * gyl0 * mk0);
        int a0x = (int)lx0, a0y = (int)ly0, b0x = (int)rx0, b0y = (int)ry0;
        bool f0 = (a0x >= tx0) & (b0x < tx0 + DTS) & (a0y >= ty0) & (b0y < ty0 + DTS);

        // ---- pixel 1 geometry ----
        float ox1 = om1[n];
        float oy1 = om1[9 + n];
        float mk1 = om1[18 + n];
        float px1 = (float)(h1 + dxi) + ox1;
        float py1 = (float)(w + dyi) + oy1;
        float qfx1 = floorf(px1), qfy1 = floorf(py1);
        float lx1 = fminf(fmaxf(qfx1, 0.f), 65.f);
        float ly1 = fminf(fmaxf(qfy1, 0.f), 65.f);
        float rx1 = fminf(fmaxf(qfx1 + 1.f, 0.f), 65.f);
        float ry1 = fminf(fmaxf(qfy1 + 1.f, 0.f), 65.f);
        float pxc1 = fminf(fmaxf(px1, 0.f), 65.f);
        float pyc1 = fminf(fmaxf(py1, 0.f), 65.f);
        float gxl1 = 1.f + lx1 - pxc1, gxr1 = 1.f - rx1 + pxc1;
        float gyl1 = 1.f + ly1 - pyc1, gyr1 = 1.f - ry1 + pyc1;
        ull g1lt = bc2(gxl1 * gyl1 * mk1), g1rb = bc2(gxr1 * gyr1 * mk1);
        ull g1lb = bc2(gxl1 * gyr1 * mk1), g1rt = bc2(gxr1 * gyl1 * mk1);
        int a1x = (int)lx1, a1y = (int)ly1, b1x = (int)rx1, b1y = (int)ry1;
        bool f1 = (a1x >= tx0) & (b1x < tx0 + DTS) & (a1y >= ty0) & (b1y < ty0 + DTS);

#pragma unroll
        for (int half = 0; half < 2; half++) {
            int co = half << 4;
            ull s2A[8], s2B[8];

            if (f0) {
                const ulonglong2* A = (const ulonglong2*)(xt + ((a0x - tx0) * DTS + (a0y - ty0)) * XSTR + co);
                const ulonglong2* B = (const ulonglong2*)(xt + ((b0x - tx0) * DTS + (b0y - ty0)) * XSTR + co);
                const ulonglong2* C = (const ulonglong2*)(xt + ((a0x - tx0) * DTS + (b0y - ty0)) * XSTR + co);
                const ulonglong2* D = (const ulonglong2*)(xt + ((b0x - tx0) * DTS + (a0y - ty0)) * XSTR + co);
#pragma unroll
                for (int q = 0; q < 4; q++) {
                    ulonglong2 a = A[q], b = B[q], c = C[q], d = D[q];
                    MUL2(s2A[2 * q],     a.x, g0lt);
                    FMA2(s2A[2 * q],     b.x, g0rb);
                    FMA2(s2A[2 * q],     c.x, g0lb);
                    FMA2(s2A[2 * q],     d.x, g0rt);
                    MUL2(s2A[2 * q + 1], a.y, g0lt);
                    FMA2(s2A[2 * q + 1], b.y, g0rb);
                    FMA2(s2A[2 * q + 1], c.y, g0lb);
                    FMA2(s2A[2 * q + 1], d.y, g0rt);
                }
            } else {
#pragma unroll
                for (int u = 0; u < 8; u++) s2A[u] = 0ull;
                add_corner_x2(s2A, x, po, a0x, a0y, g0lt, co);
                add_corner_x2(s2A, x, po, b0x, b0y, g0rb, co);
                add_corner_x2(s2A, x, po, a0x, b0y, g0lb, co);
                add_corner_x2(s2A, x, po, b0x, a0y, g0rt, co);
            }

            if (f1) {
                const ulonglong2* A = (const ulonglong2*)(xt + ((a1x - tx0) * DTS + (a1y - ty0)) * XSTR + co);
                const ulonglong2* B = (const ulonglong2*)(xt + ((b1x - tx0) * DTS + (b1y - ty0)) * XSTR + co);
                const ulonglong2* C = (const ulonglong2*)(xt + ((a1x - tx0) * DTS + (b1y - ty0)) * XSTR + co);
                const ulonglong2* D = (const ulonglong2*)(xt + ((b1x - tx0) * DTS + (a1y - ty0)) * XSTR + co);
#pragma unroll
                for (int q = 0; q < 4; q++) {
                    ulonglong2 a = A[q], b = B[q], c = C[q], d = D[q];
                    MUL2(s2B[2 * q],     a.x, g1lt);
                    FMA2(s2B[2 * q],     b.x, g1rb);
                    FMA2(s2B[2 * q],     c.x, g1lb);
                    FMA2(s2B[2 * q],     d.x, g1rt);
                    MUL2(s2B[2 * q + 1], a.y, g1lt);
                    FMA2(s2B[2 * q + 1], b.y, g1rb);
                    FMA2(s2B[2 * q + 1], c.y, g1lb);
                    FMA2(s2B[2 * q + 1], d.y, g1rt);
                }
            } else {
#pragma unroll
                for (int u = 0; u < 8; u++) s2B[u] = 0ull;
                add_corner_x2(s2B, x, po, a1x, a1y, g1lt, co);
                add_corner_x2(s2B, x, po, b1x, b1y, g1rb, co);
                add_corner_x2(s2B, x, po, a1x, b1y, g1lb, co);
                add_corner_x2(s2B, x, po, b1x, a1y, g1rt, co);
            }

#pragma unroll
            for (int u = 0; u < 8; u++) {
#pragma unroll
                for (int half2 = 0; half2 < 2; half2++) {
                    int c = co + 2 * u + half2;
                    float fa = half2 ? hi2(s2A[u]) : lo2(s2A[u]);
                    float fb = half2 ? hi2(s2B[u]) : lo2(s2B[u]);
                    ull ba = bc2(fa), bb = bc2(fb);
                    const float* wrow = &c_Wc2[(n * 32 + c) * 32];   // constant space -> LDC/LDCU
                    const ulonglong2* wc2 = (const ulonglong2*)wrow;
#pragma unroll
                    for (int k = 0; k < 7; k++) {
                        ulonglong2 wv = wc2[k];
                        FMA2(A0[2 * k],     wv.x, ba);
                        FMA2(A0[2 * k + 1], wv.y, ba);
                        FMA2(A1[2 * k],     wv.x, bb);
                        FMA2(A1[2 * k + 1], wv.y, bb);
                    }
                    ull w14 = *(const ull*)(wrow + 28);   // pair (o=28,29)
                    FMA2(A0[14], w14, ba);
                    FMA2(A1[14], w14, bb);
                }
            }
        }
    }

    int hw0 = h0 * 64 + w;
    float* yb0 = g_y1 + (size_t)j * 30 * NPIX + hw0;
    float* yb1 = yb0 + 16 * 64;
#pragma unroll
    for (int op = 0; op < 15; op++) {
        yb0[(size_t)(2 * op)     * NPIX] = lo2(A0[op]);
        yb0[(size_t)(2 * op + 1) * NPIX] = hi2(A0[op]);
        yb1[(size_t)(2 * op)     * NPIX] = lo2(A1[op]);
        yb1[(size_t)(2 * op + 1) * NPIX] = hi2(A1[op]);
    }
}

// ---------------- K3: spec conv, 3 d-outputs/thread, immediate-consume window ---
__global__ void __launch_bounds__(256) k_spec(const float* __restrict__ spec_w,
                                              float* __restrict__ out) {
    __shared__ float sw2[48 * 16];   // transposed: [c=ti*3+kd][to]
    __shared__ float bsum[32];
    int tid = threadIdx.x;
    for (int p = tid; p < 768; p += 256) {
        int to = p / 48, c = p - to * 48;
        sw2[c * 16 + to] = spec_w[p];
    }
    if (tid < 32) bsum[tid] = 0.f;
    __syncthreads();

    int bx = blockIdx.x;             // 320 = 2 b * 10 dchunk * 16 hw-blocks
    int b  = bx / 160;
    int r  = bx - b * 160;
    int dc = r >> 4;                 // 0..9
    int hw = ((r & 15) << 8) + tid;
    int d0 = dc * 3;                 // 0,3,...,27

    const float* yb = g_y1 + (size_t)b * 16 * 30 * NPIX + hw;

    ull A0[8], A1[8], A2[8], S[8], Q[8];
#pragma unroll
    for (int p = 0; p < 8; p++) {
        A0[p] = 0ull; A1[p] = 0ull; A2[p] = 0ull; S[p] = 0ull; Q[p] = 0ull;
    }

#pragma unroll
    for (int ti = 0; ti < 16; ti++) {
        const float* yt = yb + (size_t)ti * 30 * NPIX;
        float v0 = (d0 >= 1)     ? yt[(size_t)(d0 - 1) * NPIX] : 0.f;
        float v1 = yt[(size_t)d0 * NPIX];
        float v2 = yt[(size_t)(d0 + 1) * NPIX];                    // d0+1 <= 28
        float v3 = yt[(size_t)(d0 + 2) * NPIX];                    // d0+2 <= 29
        float v4 = (d0 + 3 < 30) ? yt[(size_t)(d0 + 3) * NPIX] : 0.f;
        ull b0 = bc2(v0), b1 = bc2(v1), b2 = bc2(v2), b3 = bc2(v3), b4 = bc2(v4);
        const ulonglong2* w0 = (const ulonglong2*)(sw2 + (ti * 3 + 0) * 16);
        const ulonglong2* w1 = (const ulonglong2*)(sw2 + (ti * 3 + 1) * 16);
        const ulonglong2* w2 = (const ulonglong2*)(sw2 + (ti * 3 + 2) * 16);
#pragma unroll
        for (int p4 = 0; p4 < 4; p4++) {
            ulonglong2 a0 = w0[p4], a1 = w1[p4], a2 = w2[p4];
            FMA2(A0[2 * p4],     a0.x, b0); FMA2(A0[2 * p4 + 1], a0.y, b0);
            FMA2(A0[2 * p4],     a1.x, b1); FMA2(A0[2 * p4 + 1], a1.y, b1);
            FMA2(A0[2 * p4],     a2.x, b2); FMA2(A0[2 * p4 + 1], a2.y, b2);
            FMA2(A1[2 * p4],     a0.x, b1); FMA2(A1[2 * p4 + 1], a0.y, b1);
            FMA2(A1[2 * p4],     a1.x, b2); FMA2(A1[2 * p4 + 1], a1.y, b2);
            FMA2(A1[2 * p4],     a2.x, b3); FMA2(A1[2 * p4 + 1], a2.y, b3);
            FMA2(A2[2 * p4],     a0.x, b2); FMA2(A2[2 * p4 + 1], a0.y, b2);
            FMA2(A2[2 * p4],     a1.x, b3); FMA2(A2[2 * p4 + 1], a1.y, b3);
            FMA2(A2[2 * p4],     a2.x, b4); FMA2(A2[2 * p4 + 1], a2.y, b4);
        }
    }

#pragma unroll
    for (int dd = 0; dd < 3; dd++) {
        size_t ob = ((size_t)(b * 16) * 30 + (d0 + dd)) * NPIX + hw;
#pragma unroll
        for (int p = 0; p < 8; p++) {
            ull Av = (dd == 0) ? A0[p] : (dd == 1) ? A1[p] : A2[p];
            out[ob + (size_t)(2 * p)     * 30 * NPIX] = lo2(Av);
            out[ob + (size_t)(2 * p + 1) * 30 * NPIX] = hi2(Av);
            ADD2(S[p], Av);
            FMA2(Q[p], Av, Av);
        }
    }

#pragma unroll
    for (int p = 0; p < 8; p++) {
        float s0 = lo2(S[p]), s1 = hi2(S[p]);
        float q0 = lo2(Q[p]), q1 = hi2(Q[p]);
#pragma unroll
        for (int sh = 16; sh >= 1; sh >>= 1) {
            s0 += __shfl_down_sync(0xffffffffu, s0, sh);
            s1 += __shfl_down_sync(0xffffffffu, s1, sh);
            q0 += __shfl_down_sync(0xffffffffu, q0, sh);
            q1 += __shfl_down_sync(0xffffffffu, q1, sh);
        }
        if ((tid & 31) == 0) {
            atomicAdd(&bsum[2 * p],      s0);
            atomicAdd(&bsum[2 * p + 1],  s1);
            atomicAdd(&bsum[16 + 2 * p], q0);
            atomicAdd(&bsum[17 + 2 * p], q1);
        }
    }
    __syncthreads();
    if (tid < 32) atomicAdd(&g_sums[tid], bsum[tid]);
}

// ---------------- K4: BN stats + normalize + affine + relu (fused, in place) ----
__global__ void k_bn(float* __restrict__ out, const float* __restrict__ bn_g,
                     const float* __restrict__ bn_b) {
    int i4 = blockIdx.x * 256 + threadIdx.x;   // < 983040 float4s
    int ch = (i4 / 30720) & 15;
    const float n = 245760.f;
    float mean = g_sums[ch] / n;
    float var = g_sums[16 + ch] / n - mean * mean;
    float inv = rsqrtf(var + 1e-5f);
    float gg = bn_g[ch] * inv;
    float bb = bn_b[ch] - mean * gg;
    float4 v = ((float4*)out)[i4];
    v.x = fmaxf(v.x * gg + bb, 0.f);
    v.y = fmaxf(v.y * gg + bb, 0.f);
    v.z = fmaxf(v.z * gg + bb, 0.f);
    v.w = fmaxf(v.w * gg + bb, 0.f);
    ((float4*)out)[i4] = v;
}

// ---------------- launch --------------------------------------------------------
extern "C" void kernel_launch(void* const* d_in, const int* in_sizes, int n_in,
                              void* d_out, int out_size) {
    const float* x      = (const float*)d_in[0];
    const float* p_w    = (const float*)d_in[1];
    const float* p_b    = (const float*)d_in[2];
    const float* m_w    = (const float*)d_in[3];
    const float* m_b    = (const float*)d_in[4];
    const float* conv_w = (const float*)d_in[5];
    const float* comp_w = (const float*)d_in[6];
    const float* spec_w = (const float*)d_in[7];
    const float* bn_g   = (const float*)d_in[8];
    const float* bn_b   = (const float*)d_in[9];
    float* out = (float*)d_out;

    const int SM_K = DTS * DTS * XSTR * 4 + 9 * 32 * 28 * 4 + 128;   // 219008
    cudaFuncSetAttribute(k_main, cudaFuncAttributeMaxDynamicSharedMemorySize, SM_K);

    void* wc2_dev = 0;
    cudaGetSymbolAddress(&wc2_dev, g_Wc2);

    k_prep<<<68, 256>>>(comp_w, conv_w, p_w, m_w);
    cudaMemcpyToSymbolAsync(c_Wc2, wc2_dev, 9 * 32 * 32 * sizeof(float), 0,
                            cudaMemcpyDeviceToDevice, 0);
    k_main<<<128, 512, SM_K>>>(x, p_b, m_b);
    k_spec<<<320, 256>>>(spec_w, out);
    k_bn<<<3840, 256>>>(out, bn_g, bn_b);
    (void)in_sizes; (void)n_in; (void)out_size;
}